// round 15
// baseline (speedup 1.0000x reference)
#include <cuda_runtime.h>
#include <cuda_bf16.h>
#include <cstdint>

// ---------------- problem constants ----------------
constexpr int CC    = 256;
constexpr int CSS   = 4;
constexpr int CHID  = 1024;
constexpr int MTOK  = 32 * 64 * 64;  // 131072 tokens

// ---------------- device scratch ----------------
__device__ __nv_bfloat16 g_hw  [(size_t)MTOK * CC];
__device__ __nv_bfloat16 g_qkv [(size_t)MTOK * 3 * CC];
__device__ __nv_bfloat16 g_att [(size_t)MTOK * CC];
__device__ __nv_bfloat16 g_proj[(size_t)MTOK * CC];
__device__ __nv_bfloat16 g_ln2 [(size_t)MTOK * CC];
__device__ __nv_bfloat16 g_gat [(size_t)MTOK * CHID];
__device__ __nv_bfloat16 g_wqkv [3 * CC * CC];
__device__ __nv_bfloat16 g_wproj[CC * CC];
__device__ __nv_bfloat16 g_wf12r[2 * CHID * CC];
__device__ float         g_b12r [2 * CHID];
__device__ __nv_bfloat16 g_wf2  [CC * CHID];

// ---------------- helpers ----------------
__device__ __forceinline__ float warp_sum(float v) {
#pragma unroll
    for (int o = 16; o > 0; o >>= 1) v += __shfl_xor_sync(0xffffffffu, v, o);
    return v;
}
__device__ __forceinline__ int reg3(int p) { return p < 56 ? 0 : (p < 60 ? 1 : 2); }

__device__ __forceinline__ uint32_t bf2_to_u32(float lo, float hi) {
    union { __nv_bfloat162 b; uint32_t u; } cvt;
    cvt.b = __floats2bfloat162_rn(lo, hi);
    return cvt.u;
}

__device__ __forceinline__ void cp_async16(uint32_t smem_dst, const void* gmem_src) {
    asm volatile("cp.async.cg.shared.global [%0], [%1], 16;\n" :: "r"(smem_dst), "l"(gmem_src));
}
#define CP_COMMIT() asm volatile("cp.async.commit_group;\n" ::: "memory")
#define CP_WAIT1()  asm volatile("cp.async.wait_group 1;\n" ::: "memory")
#define CP_WAIT0()  asm volatile("cp.async.wait_group 0;\n" ::: "memory")

__device__ __forceinline__ void ldsm_x4(uint32_t& r0, uint32_t& r1, uint32_t& r2, uint32_t& r3,
                                        uint32_t addr) {
    asm volatile("ldmatrix.sync.aligned.m8n8.x4.shared.b16 {%0,%1,%2,%3}, [%4];"
                 : "=r"(r0), "=r"(r1), "=r"(r2), "=r"(r3) : "r"(addr));
}
__device__ __forceinline__ void ldsm_x4_trans(uint32_t& r0, uint32_t& r1, uint32_t& r2, uint32_t& r3,
                                              uint32_t addr) {
    asm volatile("ldmatrix.sync.aligned.m8n8.x4.trans.shared.b16 {%0,%1,%2,%3}, [%4];"
                 : "=r"(r0), "=r"(r1), "=r"(r2), "=r"(r3) : "r"(addr));
}
__device__ __forceinline__ void mma16816(float* d, const uint32_t* a, const uint32_t* b) {
    asm volatile(
        "mma.sync.aligned.m16n8k16.row.col.f32.bf16.bf16.f32 "
        "{%0,%1,%2,%3}, {%4,%5,%6,%7}, {%8,%9}, {%0,%1,%2,%3};"
        : "+f"(d[0]), "+f"(d[1]), "+f"(d[2]), "+f"(d[3])
        : "r"(a[0]), "r"(a[1]), "r"(a[2]), "r"(a[3]), "r"(b[0]), "r"(b[1]));
}

// ---------------- unified weight prep (one launch) ----------------
__global__ void k_prep(const float* __restrict__ qkvw, const float* __restrict__ projw,
                       const float* __restrict__ f2w, const float* __restrict__ f12w,
                       const float* __restrict__ f12b,
                       __nv_bfloat16* __restrict__ wq, __nv_bfloat16* __restrict__ wp,
                       __nv_bfloat16* __restrict__ w2, __nv_bfloat16* __restrict__ w12r,
                       float* __restrict__ b12r) {
    int i = blockIdx.x * blockDim.x + threadIdx.x;
    if (i < 524288) {
        int r = i >> 8, c = i & 255;
        int src = (r & 1) ? (r >> 1) + 1024 : (r >> 1);
        w12r[i] = __float2bfloat16(f12w[src * 256 + c]);
    }
    if (i < 262144) w2[i] = __float2bfloat16(f2w[i]);
    if (i < 196608) wq[i] = __float2bfloat16(qkvw[i]);
    if (i < 65536)  wp[i] = __float2bfloat16(projw[i]);
    if (i < 2048) {
        int src = (i & 1) ? (i >> 1) + 1024 : (i >> 1);
        b12r[i] = f12b[src];
    }
}

// ---------------- persistent mma.sync GEMM: BK=64, 3-slot ring across tiles ----------------
// Tile 128x128, 8 warps (2m x 4n), warp tile 64x32, 2 CTAs/SM, grid = 2*SMs.
// Flattened chunk index j over (tile, kt) keeps cp.async pipeline full across tiles.
// EPI: 0 = bf16 + bias | 3 = SiLU-gated pairs | 4 = f32 + bias + recomputed resid (x + proj)
constexpr int MLDA  = 72;
constexpr int STG_A = 128 * MLDA;
constexpr int STG_B = 128 * MLDA;
constexpr int STG_E = STG_A + STG_B;
constexpr int M3_SMEM = 3 * STG_E * 2;         // 110592 bytes (2 CTAs/SM)

template <int KTL>
__device__ __forceinline__ void p_stage_load(
    const __nv_bfloat16* __restrict__ A, const __nv_bfloat16* __restrict__ W,
    uint32_t sbase, int slot, int j, int bx, int G, int NX, int K, int tid) {
    int tile = bx + (j >> KTL) * G;
    int m0 = (tile / NX) << 7;
    int n0 = (tile % NX) << 7;
    int k0 = (j & ((1 << KTL) - 1)) << 6;
    uint32_t st = sbase + (uint32_t)(slot * STG_E * 2);
#pragma unroll
    for (int u = 0; u < 4; u++) {
        int ch = tid + (u << 8);
        int row = ch >> 3, c = (ch & 7) << 3;
        cp_async16(st + (uint32_t)((row * MLDA + c) * 2),
                   A + (size_t)(m0 + row) * K + k0 + c);
    }
    uint32_t stb = st + STG_A * 2;
#pragma unroll
    for (int u = 0; u < 4; u++) {
        int ch = tid + (u << 8);
        int row = ch >> 3, c = (ch & 7) << 3;
        cp_async16(stb + (uint32_t)((row * MLDA + c) * 2),
                   W + (size_t)(n0 + row) * K + k0 + c);
    }
}

template <int EPI, int KTL>
__global__ void __launch_bounds__(256, 2)
k_gemm3(const __nv_bfloat16* __restrict__ A, const __nv_bfloat16* __restrict__ W,
        const float* __restrict__ bias, void* __restrict__ Cp,
        const float* __restrict__ resid, const __nv_bfloat16* __restrict__ proj2,
        int M, int N, int K, int NX) {
    extern __shared__ __align__(16) char dsm[];
    const uint32_t sbase = (uint32_t)__cvta_generic_to_shared(dsm);

    const int tid  = threadIdx.x;
    const int lane = tid & 31;
    const int warp = tid >> 5;
    const int wm   = warp >> 2;
    const int wn   = warp & 3;
    const int KT   = 1 << KTL;
    const int NT   = (M >> 7) * NX;
    const int bx   = blockIdx.x;
    const int G    = gridDim.x;
    const int nloc = (NT - bx + G - 1) / G;
    if (nloc <= 0) return;
    const int J = nloc << KTL;

    const int aRow  = wm * 64 + (lane & 15);
    const int aColH = (lane >> 4) << 3;
    const int bRow  = wn * 32 + (lane & 7) + ((lane >> 4) << 3);
    const int bColH = ((lane >> 3) & 1) << 3;

    float d[4][4][4];
#pragma unroll
    for (int i = 0; i < 4; i++)
#pragma unroll
        for (int jj = 0; jj < 4; jj++)
#pragma unroll
            for (int e = 0; e < 4; e++) d[i][jj][e] = 0.f;

    // prologue: chunks 0, 1
    p_stage_load<KTL>(A, W, sbase, 0, 0, bx, G, NX, K, tid); CP_COMMIT();
    p_stage_load<KTL>(A, W, sbase, 1, 1, bx, G, NX, K, tid); CP_COMMIT();

    int slot = 0;
    for (int j = 0; j < J; j++) {
        CP_WAIT1();
        __syncthreads();
        if (j + 2 < J) {
            int ns = slot + 2; if (ns >= 3) ns -= 3;
            p_stage_load<KTL>(A, W, sbase, ns, j + 2, bx, G, NX, K, tid);
        }
        CP_COMMIT();

        const uint32_t stA = sbase + (uint32_t)((slot * STG_E) * 2);
        const uint32_t stB = stA + (uint32_t)(STG_A * 2);
#pragma unroll
        for (int kk = 0; kk < 64; kk += 16) {
            uint32_t a[4][4];
#pragma unroll
            for (int mi = 0; mi < 4; mi++)
                ldsm_x4(a[mi][0], a[mi][1], a[mi][2], a[mi][3],
                        stA + (uint32_t)(((aRow + mi * 16) * MLDA + kk + aColH) * 2));
            uint32_t b[4][2];
#pragma unroll
            for (int ni = 0; ni < 2; ni++) {
                uint32_t r0, r1, r2, r3;
                ldsm_x4(r0, r1, r2, r3,
                        stB + (uint32_t)(((bRow + ni * 16) * MLDA + kk + bColH) * 2));
                b[ni * 2][0] = r0; b[ni * 2][1] = r1;
                b[ni * 2 + 1][0] = r2; b[ni * 2 + 1][1] = r3;
            }
#pragma unroll
            for (int mi = 0; mi < 4; mi++)
#pragma unroll
                for (int nj = 0; nj < 4; nj++)
                    mma16816(d[mi][nj], a[mi], b[nj]);
        }
        if (++slot == 3) slot = 0;

        if ((j & (KT - 1)) == KT - 1) {
            // ---- register-direct epilogue for the tile just finished ----
            const int tile = bx + (j >> KTL) * G;
            const int m0 = (tile / NX) << 7;
            const int n0 = (tile % NX) << 7;
            const int rb = m0 + wm * 64 + (lane >> 2);
            const int cb = n0 + wn * 32 + ((lane & 3) << 1);
#pragma unroll
            for (int mi = 0; mi < 4; mi++) {
#pragma unroll
                for (int nj = 0; nj < 4; nj++) {
                    const int c = cb + nj * 8;
                    const float2 bv = *(const float2*)(bias + c);
#pragma unroll
                    for (int h = 0; h < 2; h++) {
                        const int r = rb + mi * 16 + h * 8;
                        const float v0 = d[mi][nj][h * 2]     + bv.x;
                        const float v1 = d[mi][nj][h * 2 + 1] + bv.y;
                        if (EPI == 0) {
                            __nv_bfloat162 o = __floats2bfloat162_rn(v0, v1);
                            *(__nv_bfloat162*)((__nv_bfloat16*)Cp + (size_t)r * N + c) = o;
                        } else if (EPI == 4) {
                            int b_ = r >> 12, pos = r & 4095;
                            int hh = pos >> 6, ww = pos & 63;
                            int hs = (hh - CSS) & 63, ws = (ww - CSS) & 63;
                            int m = (b_ << 12) + ((((hs >> 3) << 3) + (ws >> 3)) << 6)
                                    + ((hs & 7) << 3) + (ws & 7);
                            size_t off = (size_t)r * N + c;
                            float2 xv = *(const float2*)(resid + off);
                            __nv_bfloat162 pv =
                                *(const __nv_bfloat162*)(proj2 + (size_t)m * 256 + c);
                            float2 pf = __bfloat1622float2(pv);
                            float2 o = {v0 + xv.x + pf.x, v1 + xv.y + pf.y};
                            *(float2*)((float*)Cp + off) = o;
                        } else {  // EPI == 3
                            float sg = v0 / (1.f + __expf(-v0));
                            ((__nv_bfloat16*)Cp)[(size_t)r * (N >> 1) + (c >> 1)] =
                                __float2bfloat16(sg * v1);
                        }
                    }
                }
            }
#pragma unroll
            for (int i = 0; i < 4; i++)
#pragma unroll
                for (int jj = 0; jj < 4; jj++)
#pragma unroll
                    for (int e = 0; e < 4; e++) d[i][jj][e] = 0.f;
        }
    }
}

// ---------------- LN1 + cyclic shift + window partition ----------------
__global__ void k_ln1_shift(const float* __restrict__ x, const float* __restrict__ w,
                            const float* __restrict__ bb, __nv_bfloat16* __restrict__ out) {
    int gw = (blockIdx.x * blockDim.x + threadIdx.x) >> 5;
    int lane = threadIdx.x & 31;
    if (gw >= MTOK) return;
    int b = gw >> 12, r = gw & 4095;
    int wi = r >> 6, n = r & 63;
    int hs = ((wi >> 3) << 3) + (n >> 3);
    int ws = ((wi & 7) << 3) + (n & 7);
    int h0 = (hs + CSS) & 63, w0 = (ws + CSS) & 63;
    const float4* row = (const float4*)(x + ((size_t)(b << 12) + (h0 << 6) + w0) * CC);
    float4 a = row[lane * 2], c = row[lane * 2 + 1];
    float s  = a.x + a.y + a.z + a.w + c.x + c.y + c.z + c.w;
    float sq = a.x*a.x + a.y*a.y + a.z*a.z + a.w*a.w + c.x*c.x + c.y*c.y + c.z*c.z + c.w*c.w;
    s = warp_sum(s); sq = warp_sum(sq);
    float mean = s * (1.f / 256.f);
    float var  = sq * (1.f / 256.f) - mean * mean;
    float rs   = rsqrtf(var + 1e-5f);
    const float4* wp = (const float4*)w;
    const float4* bp = (const float4*)bb;
    float4 w0v = wp[lane * 2], w1v = wp[lane * 2 + 1];
    float4 b0v = bp[lane * 2], b1v = bp[lane * 2 + 1];
    __align__(16) __nv_bfloat16 o8[8];
    o8[0] = __float2bfloat16((a.x - mean) * rs * w0v.x + b0v.x);
    o8[1] = __float2bfloat16((a.y - mean) * rs * w0v.y + b0v.y);
    o8[2] = __float2bfloat16((a.z - mean) * rs * w0v.z + b0v.z);
    o8[3] = __float2bfloat16((a.w - mean) * rs * w0v.w + b0v.w);
    o8[4] = __float2bfloat16((c.x - mean) * rs * w1v.x + b1v.x);
    o8[5] = __float2bfloat16((c.y - mean) * rs * w1v.y + b1v.y);
    o8[6] = __float2bfloat16((c.z - mean) * rs * w1v.z + b1v.z);
    o8[7] = __float2bfloat16((c.w - mean) * rs * w1v.w + b1v.w);
    *(uint4*)(out + (size_t)gw * CC + lane * 8) = *(const uint4*)o8;
}

// ---------------- tensor-core attention (R13 shape — validated) ----------------
constexpr int ATT_STRIDE = 776;
constexpr int ATT_TILE_B = 64 * ATT_STRIDE * 2;
constexpr int ATT_SMEM   = ATT_TILE_B + 1800 * 4;

__global__ void __launch_bounds__(512, 1)
k_attn2(const __nv_bfloat16* __restrict__ qkv, const float* __restrict__ rpb,
        __nv_bfloat16* __restrict__ out) {
    extern __shared__ __align__(16) char asmem[];
    const uint32_t sb = (uint32_t)__cvta_generic_to_shared(asmem);
    const float* bias_sm = (const float*)(asmem + ATT_TILE_B);
    const int win  = blockIdx.x;
    const int tid  = threadIdx.x;
    const int lane = tid & 31;
    const int warp = tid >> 5;
    const int h    = warp >> 1;
    const int rh   = warp & 1;
    const int rbase = rh * 32;

    {
        const __nv_bfloat16* src = qkv + (size_t)win * 64 * 768;
        for (int i = tid; i < 6144; i += 512) {
            int row = i / 96, c = (i % 96) << 3;
            cp_async16(sb + (uint32_t)((row * ATT_STRIDE + c) * 2), src + row * 768 + c);
        }
        uint32_t bb = sb + ATT_TILE_B;
        for (int i = tid; i < 450; i += 512)
            cp_async16(bb + (uint32_t)(i * 16), rpb + i * 4);
    }
    CP_COMMIT();
    CP_WAIT0();
    __syncthreads();

    const int qcol = h * 32, kcol = 256 + h * 32, vcol = 512 + h * 32;

    float s[2][8][4];
#pragma unroll
    for (int mi = 0; mi < 2; mi++)
#pragma unroll
        for (int nj = 0; nj < 8; nj++)
#pragma unroll
            for (int e = 0; e < 4; e++) s[mi][nj][e] = 0.f;

#pragma unroll
    for (int ks = 0; ks < 32; ks += 16) {
        uint32_t a[2][4];
#pragma unroll
        for (int mi = 0; mi < 2; mi++)
            ldsm_x4(a[mi][0], a[mi][1], a[mi][2], a[mi][3],
                    sb + (uint32_t)(((rbase + mi * 16 + (lane & 15)) * ATT_STRIDE
                                     + qcol + ks + ((lane >> 4) << 3)) * 2));
        uint32_t b[8][2];
#pragma unroll
        for (int ni = 0; ni < 4; ni++) {
            uint32_t r0, r1, r2, r3;
            ldsm_x4(r0, r1, r2, r3,
                    sb + (uint32_t)(((ni * 16 + (lane & 7) + ((lane >> 4) << 3)) * ATT_STRIDE
                                     + kcol + ks + (((lane >> 3) & 1) << 3)) * 2));
            b[ni * 2][0] = r0; b[ni * 2][1] = r1;
            b[ni * 2 + 1][0] = r2; b[ni * 2 + 1][1] = r3;
        }
#pragma unroll
        for (int mi = 0; mi < 2; mi++)
#pragma unroll
            for (int nj = 0; nj < 8; nj++)
                mma16816(s[mi][nj], a[mi], b[nj]);
    }

    const int wi = win & 63;
    const int wr = (wi >> 3) << 3, wc = (wi & 7) << 3;
    const float scale = 0.17677669529663687f;
    float mx[2][2] = {{-1e30f,-1e30f},{-1e30f,-1e30f}};
#pragma unroll
    for (int mi = 0; mi < 2; mi++)
#pragma unroll
        for (int h8 = 0; h8 < 2; h8++) {
            int qi = rbase + mi * 16 + (lane >> 2) + h8 * 8;
            int qri = qi >> 3, qci = qi & 7;
            int myid = reg3(wr + qri) * 3 + reg3(wc + qci);
#pragma unroll
            for (int nj = 0; nj < 8; nj++)
#pragma unroll
                for (int e = 0; e < 2; e++) {
                    int kj = nj * 8 + ((lane & 3) << 1) + e;
                    int krj = kj >> 3, kcj = kj & 7;
                    float v = fmaf(s[mi][nj][h8 * 2 + e], scale,
                                   bias_sm[(((qri - krj + 7) * 15 + qci - kcj + 7) << 3) + h]);
                    int jid = reg3(wr + krj) * 3 + reg3(wc + kcj);
                    if (jid != myid) v -= 100.f;
                    s[mi][nj][h8 * 2 + e] = v;
                    mx[mi][h8] = fmaxf(mx[mi][h8], v);
                }
        }
#pragma unroll
    for (int mi = 0; mi < 2; mi++)
#pragma unroll
        for (int h8 = 0; h8 < 2; h8++) {
            mx[mi][h8] = fmaxf(mx[mi][h8], __shfl_xor_sync(0xffffffffu, mx[mi][h8], 1));
            mx[mi][h8] = fmaxf(mx[mi][h8], __shfl_xor_sync(0xffffffffu, mx[mi][h8], 2));
        }

    float sum[2][2] = {{0,0},{0,0}};
#pragma unroll
    for (int mi = 0; mi < 2; mi++)
#pragma unroll
        for (int nj = 0; nj < 8; nj++)
#pragma unroll
            for (int e4 = 0; e4 < 4; e4++) {
                int h8 = e4 >> 1;
                float v = __expf(s[mi][nj][e4] - mx[mi][h8]);
                s[mi][nj][e4] = v;
                sum[mi][h8] += v;
            }
    float inv[2][2];
#pragma unroll
    for (int mi = 0; mi < 2; mi++)
#pragma unroll
        for (int h8 = 0; h8 < 2; h8++) {
            float t = sum[mi][h8];
            t += __shfl_xor_sync(0xffffffffu, t, 1);
            t += __shfl_xor_sync(0xffffffffu, t, 2);
            inv[mi][h8] = __frcp_rn(t);
        }

    uint32_t p[2][4][4];
#pragma unroll
    for (int mi = 0; mi < 2; mi++)
#pragma unroll
        for (int ks = 0; ks < 4; ks++) {
            p[mi][ks][0] = bf2_to_u32(s[mi][2*ks][0],   s[mi][2*ks][1]);
            p[mi][ks][1] = bf2_to_u32(s[mi][2*ks][2],   s[mi][2*ks][3]);
            p[mi][ks][2] = bf2_to_u32(s[mi][2*ks+1][0], s[mi][2*ks+1][1]);
            p[mi][ks][3] = bf2_to_u32(s[mi][2*ks+1][2], s[mi][2*ks+1][3]);
        }

    float o[2][4][4];
#pragma unroll
    for (int mi = 0; mi < 2; mi++)
#pragma unroll
        for (int dj = 0; dj < 4; dj++)
#pragma unroll
            for (int e = 0; e < 4; e++) o[mi][dj][e] = 0.f;

#pragma unroll
    for (int ks = 0; ks < 4; ks++) {
        uint32_t vb[4][2];
#pragma unroll
        for (int dt = 0; dt < 2; dt++) {
            uint32_t r0, r1, r2, r3;
            ldsm_x4_trans(r0, r1, r2, r3,
                sb + (uint32_t)(((ks * 16 + (lane & 7) + (((lane >> 3) & 1) << 3)) * ATT_STRIDE
                                 + vcol + dt * 16 + ((lane >> 4) << 3)) * 2));
            vb[dt * 2][0] = r0; vb[dt * 2][1] = r1;
            vb[dt * 2 + 1][0] = r2; vb[dt * 2 + 1][1] = r3;
        }
#pragma unroll
        for (int mi = 0; mi < 2; mi++)
#pragma unroll
            for (int dj = 0; dj < 4; dj++)
                mma16816(o[mi][dj], p[mi][ks], vb[dj]);
    }

#pragma unroll
    for (int mi = 0; mi < 2; mi++)
#pragma unroll
        for (int dj = 0; dj < 4; dj++)
#pragma unroll
            for (int h8 = 0; h8 < 2; h8++) {
                int row = rbase + mi * 16 + (lane >> 2) + h8 * 8;
                int col = dj * 8 + ((lane & 3) << 1);
                __nv_bfloat162 ov = __floats2bfloat162_rn(
                    o[mi][dj][h8 * 2]     * inv[mi][h8],
                    o[mi][dj][h8 * 2 + 1] * inv[mi][h8]);
                *(__nv_bfloat162*)(out + (size_t)(win * 64 + row) * 256 + h * 32 + col) = ov;
            }
}

// ---------------- residual (window-reverse + unshift) + LN2 ----------------
__global__ void k_resid_ln2(const float* __restrict__ x, const __nv_bfloat16* __restrict__ proj,
                            const float* __restrict__ w, const float* __restrict__ bb,
                            __nv_bfloat16* __restrict__ ln2) {
    int gw = (blockIdx.x * blockDim.x + threadIdx.x) >> 5;
    int lane = threadIdx.x & 31;
    if (gw >= MTOK) return;
    int b = gw >> 12, pos = gw & 4095;
    int hh = pos >> 6, ww = pos & 63;
    int hs = (hh - CSS) & 63, ws = (ww - CSS) & 63;
    int m = (b << 12) + ((((hs >> 3) << 3) + (ws >> 3)) << 6) + ((hs & 7) << 3) + (ws & 7);
    const float4* xr = (const float4*)(x + (size_t)gw * CC);
    float4 a = xr[lane * 2], c = xr[lane * 2 + 1];
    uint4 pu = *(const uint4*)(proj + (size_t)m * CC + lane * 8);
    const __nv_bfloat162* p2 = (const __nv_bfloat162*)&pu;
    float2 f0 = __bfloat1622float2(p2[0]);
    float2 f1 = __bfloat1622float2(p2[1]);
    float2 f2 = __bfloat1622float2(p2[2]);
    float2 f3 = __bfloat1622float2(p2[3]);
    a.x += f0.x; a.y += f0.y; a.z += f1.x; a.w += f1.y;
    c.x += f2.x; c.y += f2.y; c.z += f3.x; c.w += f3.y;
    float s  = a.x + a.y + a.z + a.w + c.x + c.y + c.z + c.w;
    float sq = a.x*a.x + a.y*a.y + a.z*a.z + a.w*a.w + c.x*c.x + c.y*c.y + c.z*c.z + c.w*c.w;
    s = warp_sum(s); sq = warp_sum(sq);
    float mean = s * (1.f / 256.f);
    float var  = sq * (1.f / 256.f) - mean * mean;
    float rs   = rsqrtf(var + 1e-5f);
    const float4* wp = (const float4*)w;
    const float4* bp = (const float4*)bb;
    float4 w0v = wp[lane * 2], w1v = wp[lane * 2 + 1];
    float4 b0v = bp[lane * 2], b1v = bp[lane * 2 + 1];
    __align__(16) __nv_bfloat16 o8[8];
    o8[0] = __float2bfloat16((a.x - mean) * rs * w0v.x + b0v.x);
    o8[1] = __float2bfloat16((a.y - mean) * rs * w0v.y + b0v.y);
    o8[2] = __float2bfloat16((a.z - mean) * rs * w0v.z + b0v.z);
    o8[3] = __float2bfloat16((a.w - mean) * rs * w0v.w + b0v.w);
    o8[4] = __float2bfloat16((c.x - mean) * rs * w1v.x + b1v.x);
    o8[5] = __float2bfloat16((c.y - mean) * rs * w1v.y + b1v.y);
    o8[6] = __float2bfloat16((c.z - mean) * rs * w1v.z + b1v.z);
    o8[7] = __float2bfloat16((c.w - mean) * rs * w1v.w + b1v.w);
    *(uint4*)(ln2 + (size_t)gw * CC + lane * 8) = *(const uint4*)o8;
}

// ---------------- launcher ----------------
extern "C" void kernel_launch(void* const* d_in, const int* in_sizes, int n_in,
                              void* d_out, int out_size) {
    const float* x     = (const float*)d_in[0];
    const float* n1w   = (const float*)d_in[1];
    const float* n1b   = (const float*)d_in[2];
    const float* qkvw  = (const float*)d_in[3];
    const float* qkvb  = (const float*)d_in[4];
    const float* projw = (const float*)d_in[5];
    const float* projb = (const float*)d_in[6];
    const float* rpb   = (const float*)d_in[7];
    const float* n2w   = (const float*)d_in[8];
    const float* n2b   = (const float*)d_in[9];
    const float* f12w  = (const float*)d_in[10];
    const float* f12b  = (const float*)d_in[11];
    const float* f2w   = (const float*)d_in[12];
    const float* f2b   = (const float*)d_in[13];
    float* out = (float*)d_out;

    void *p_hw, *p_qkv, *p_att, *p_proj, *p_ln2, *p_gat;
    void *p_wq, *p_wp, *p_w12, *p_b12, *p_w2;
    cudaGetSymbolAddress(&p_hw, g_hw);
    cudaGetSymbolAddress(&p_qkv, g_qkv);
    cudaGetSymbolAddress(&p_att, g_att);
    cudaGetSymbolAddress(&p_proj, g_proj);
    cudaGetSymbolAddress(&p_ln2, g_ln2);
    cudaGetSymbolAddress(&p_gat, g_gat);
    cudaGetSymbolAddress(&p_wq, g_wqkv);
    cudaGetSymbolAddress(&p_wp, g_wproj);
    cudaGetSymbolAddress(&p_w12, g_wf12r);
    cudaGetSymbolAddress(&p_b12, g_b12r);
    cudaGetSymbolAddress(&p_w2, g_wf2);

    cudaFuncSetAttribute((const void*)k_gemm3<0, 2>,
                         cudaFuncAttributeMaxDynamicSharedMemorySize, M3_SMEM);
    cudaFuncSetAttribute((const void*)k_gemm3<3, 2>,
                         cudaFuncAttributeMaxDynamicSharedMemorySize, M3_SMEM);
    cudaFuncSetAttribute((const void*)k_gemm3<4, 4>,
                         cudaFuncAttributeMaxDynamicSharedMemorySize, M3_SMEM);
    cudaFuncSetAttribute(k_attn2, cudaFuncAttributeMaxDynamicSharedMemorySize, ATT_SMEM);

    int smc = 148;
    cudaDeviceGetAttribute(&smc, cudaDevAttrMultiProcessorCount, 0);
    const int PG = smc * 2;   // persistent grid: 2 CTAs per SM

    // one prep launch for all weights
    k_prep<<<2048, 256>>>(qkvw, projw, f2w, f12w, f12b,
                          (__nv_bfloat16*)p_wq, (__nv_bfloat16*)p_wp,
                          (__nv_bfloat16*)p_w2, (__nv_bfloat16*)p_w12, (float*)p_b12);

    // LN1 + shift + window partition
    k_ln1_shift<<<16384, 256>>>(x, n1w, n1b, (__nv_bfloat16*)p_hw);

    // qkv: [131072,256] @ [768,256]^T -> bf16  (NX=6)
    k_gemm3<0, 2><<<PG, 256, M3_SMEM>>>(
        (const __nv_bfloat16*)p_hw, (const __nv_bfloat16*)p_wq, qkvb,
        p_qkv, nullptr, nullptr, MTOK, 768, 256, 6);

    // tensor-core windowed attention (512 thr, 2 warps/head)
    k_attn2<<<2048, 512, ATT_SMEM>>>((const __nv_bfloat16*)p_qkv, rpb,
                                     (__nv_bfloat16*)p_att);

    // proj -> bf16 (window order)  (NX=2)
    k_gemm3<0, 2><<<PG, 256, M3_SMEM>>>(
        (const __nv_bfloat16*)p_att, (const __nv_bfloat16*)p_wp, projb,
        p_proj, nullptr, nullptr, MTOK, 256, 256, 2);

    // residual (window reverse + unshift) + LN2
    k_resid_ln2<<<16384, 256>>>(x, (const __nv_bfloat16*)p_proj, n2w, n2b,
                                (__nv_bfloat16*)p_ln2);

    // fc12 (fused SiLU gate): [131072,256] @ [2048,256]^T -> [131072,1024] bf16  (NX=16)
    k_gemm3<3, 2><<<PG, 256, M3_SMEM>>>(
        (const __nv_bfloat16*)p_ln2, (const __nv_bfloat16*)p_w12, (const float*)p_b12,
        p_gat, nullptr, nullptr, MTOK, 2048, 256, 16);

    // fc2 + recomputed residual (x + proj) -> d_out fp32  (NX=2, K=1024 -> KTL=4)
    k_gemm3<4, 4><<<PG, 256, M3_SMEM>>>(
        (const __nv_bfloat16*)p_gat, (const __nv_bfloat16*)p_w2, f2b,
        out, x, (const __nv_bfloat16*)p_proj, MTOK, 256, 1024, 2);
}

// round 16
// speedup vs baseline: 1.0867x; 1.0867x over previous
#include <cuda_runtime.h>
#include <cuda_bf16.h>
#include <cstdint>

// ---------------- problem constants ----------------
constexpr int CC    = 256;
constexpr int CSS   = 4;
constexpr int CHID  = 1024;
constexpr int MTOK  = 32 * 64 * 64;  // 131072 tokens

// ---------------- device scratch ----------------
__device__ __nv_bfloat16 g_hw  [(size_t)MTOK * CC];
__device__ __nv_bfloat16 g_qkv [(size_t)MTOK * 3 * CC];
__device__ __nv_bfloat16 g_att [(size_t)MTOK * CC];
__device__ __nv_bfloat16 g_proj[(size_t)MTOK * CC];
__device__ __nv_bfloat16 g_ln2 [(size_t)MTOK * CC];
__device__ __nv_bfloat16 g_gat [(size_t)MTOK * CHID];
__device__ __nv_bfloat16 g_wqkv [3 * CC * CC];
__device__ __nv_bfloat16 g_wproj[CC * CC];
__device__ __nv_bfloat16 g_wf12r[2 * CHID * CC];
__device__ float         g_b12r [2 * CHID];
__device__ __nv_bfloat16 g_wf2  [CC * CHID];

// ---------------- helpers ----------------
__device__ __forceinline__ float warp_sum(float v) {
#pragma unroll
    for (int o = 16; o > 0; o >>= 1) v += __shfl_xor_sync(0xffffffffu, v, o);
    return v;
}
__device__ __forceinline__ int reg3(int p) { return p < 56 ? 0 : (p < 60 ? 1 : 2); }

__device__ __forceinline__ uint32_t bf2_to_u32(float lo, float hi) {
    union { __nv_bfloat162 b; uint32_t u; } cvt;
    cvt.b = __floats2bfloat162_rn(lo, hi);
    return cvt.u;
}

__device__ __forceinline__ void cp_async16(uint32_t smem_dst, const void* gmem_src) {
    asm volatile("cp.async.cg.shared.global [%0], [%1], 16;\n" :: "r"(smem_dst), "l"(gmem_src));
}
#define CP_COMMIT() asm volatile("cp.async.commit_group;\n" ::: "memory")
#define CP_WAIT1()  asm volatile("cp.async.wait_group 1;\n" ::: "memory")
#define CP_WAIT0()  asm volatile("cp.async.wait_group 0;\n" ::: "memory")

__device__ __forceinline__ void ldsm_x4(uint32_t& r0, uint32_t& r1, uint32_t& r2, uint32_t& r3,
                                        uint32_t addr) {
    asm volatile("ldmatrix.sync.aligned.m8n8.x4.shared.b16 {%0,%1,%2,%3}, [%4];"
                 : "=r"(r0), "=r"(r1), "=r"(r2), "=r"(r3) : "r"(addr));
}
__device__ __forceinline__ void ldsm_x4_trans(uint32_t& r0, uint32_t& r1, uint32_t& r2, uint32_t& r3,
                                              uint32_t addr) {
    asm volatile("ldmatrix.sync.aligned.m8n8.x4.trans.shared.b16 {%0,%1,%2,%3}, [%4];"
                 : "=r"(r0), "=r"(r1), "=r"(r2), "=r"(r3) : "r"(addr));
}
__device__ __forceinline__ void mma16816(float* d, const uint32_t* a, const uint32_t* b) {
    asm volatile(
        "mma.sync.aligned.m16n8k16.row.col.f32.bf16.bf16.f32 "
        "{%0,%1,%2,%3}, {%4,%5,%6,%7}, {%8,%9}, {%0,%1,%2,%3};"
        : "+f"(d[0]), "+f"(d[1]), "+f"(d[2]), "+f"(d[3])
        : "r"(a[0]), "r"(a[1]), "r"(a[2]), "r"(a[3]), "r"(b[0]), "r"(b[1]));
}

// ---------------- unified weight prep (one launch) ----------------
__global__ void k_prep(const float* __restrict__ qkvw, const float* __restrict__ projw,
                       const float* __restrict__ f2w, const float* __restrict__ f12w,
                       const float* __restrict__ f12b,
                       __nv_bfloat16* __restrict__ wq, __nv_bfloat16* __restrict__ wp,
                       __nv_bfloat16* __restrict__ w2, __nv_bfloat16* __restrict__ w12r,
                       float* __restrict__ b12r) {
    int i = blockIdx.x * blockDim.x + threadIdx.x;
    if (i < 524288) {
        int r = i >> 8, c = i & 255;
        int src = (r & 1) ? (r >> 1) + 1024 : (r >> 1);
        w12r[i] = __float2bfloat16(f12w[src * 256 + c]);
    }
    if (i < 262144) w2[i] = __float2bfloat16(f2w[i]);
    if (i < 196608) wq[i] = __float2bfloat16(qkvw[i]);
    if (i < 65536)  wp[i] = __float2bfloat16(projw[i]);
    if (i < 2048) {
        int src = (i & 1) ? (i >> 1) + 1024 : (i >> 1);
        b12r[i] = f12b[src];
    }
}

// ---------------- mma.sync GEMM: BK=64, 3 stages, 2 CTAs/SM (R14 — validated) ----------------
// Tile 128x128, 8 warps (2m x 4n), warp tile 64x32.
// EPI: 0 = bf16 + bias | 3 = SiLU-gated pairs | 4 = f32 + bias + recomputed resid (x + proj)
constexpr int MLDA  = 72;
constexpr int STG_A = 128 * MLDA;
constexpr int STG_B = 128 * MLDA;
constexpr int STG_E = STG_A + STG_B;
constexpr int M3_SMEM = 3 * STG_E * 2;         // 110592 bytes (2 CTAs/SM)

__device__ __forceinline__ void m3_stage_load(
    const __nv_bfloat16* __restrict__ A, const __nv_bfloat16* __restrict__ W,
    uint32_t sbase, int slot, int k0, int m0, int n0, int K, int tid) {
    uint32_t st = sbase + (uint32_t)(slot * STG_E * 2);
#pragma unroll
    for (int u = 0; u < 4; u++) {
        int ch = tid + (u << 8);
        int row = ch >> 3, c = (ch & 7) << 3;
        cp_async16(st + (uint32_t)((row * MLDA + c) * 2),
                   A + (size_t)(m0 + row) * K + k0 + c);
    }
    uint32_t stb = st + STG_A * 2;
#pragma unroll
    for (int u = 0; u < 4; u++) {
        int ch = tid + (u << 8);
        int row = ch >> 3, c = (ch & 7) << 3;
        cp_async16(stb + (uint32_t)((row * MLDA + c) * 2),
                   W + (size_t)(n0 + row) * K + k0 + c);
    }
}

template <int EPI>
__global__ void __launch_bounds__(256, 2)
k_gemm3(const __nv_bfloat16* __restrict__ A, const __nv_bfloat16* __restrict__ W,
        const float* __restrict__ bias, void* __restrict__ Cp,
        const float* __restrict__ resid, const __nv_bfloat16* __restrict__ proj2,
        int M, int N, int K) {
    extern __shared__ __align__(16) char dsm[];
    const uint32_t sbase = (uint32_t)__cvta_generic_to_shared(dsm);

    const int tid  = threadIdx.x;
    const int lane = tid & 31;
    const int warp = tid >> 5;
    const int wm   = warp >> 2;
    const int wn   = warp & 3;
    const int m0 = blockIdx.y << 7;
    const int n0 = blockIdx.x << 7;
    const int KT = K >> 6;

    const int aRow  = wm * 64 + (lane & 15);
    const int aColH = (lane >> 4) << 3;
    const int bRow  = wn * 32 + (lane & 7) + ((lane >> 4) << 3);
    const int bColH = ((lane >> 3) & 1) << 3;

    float d[4][4][4];
#pragma unroll
    for (int i = 0; i < 4; i++)
#pragma unroll
        for (int j = 0; j < 4; j++)
#pragma unroll
            for (int e = 0; e < 4; e++) d[i][j][e] = 0.f;

#pragma unroll
    for (int s = 0; s < 2; s++) {
        m3_stage_load(A, W, sbase, s, s << 6, m0, n0, K, tid);
        CP_COMMIT();
    }

    int slot = 0;
    for (int kt = 0; kt < KT; kt++) {
        CP_WAIT1();
        __syncthreads();
        if (kt + 2 < KT) {
            int ns = slot + 2; if (ns >= 3) ns -= 3;
            m3_stage_load(A, W, sbase, ns, (kt + 2) << 6, m0, n0, K, tid);
        }
        CP_COMMIT();

        const uint32_t stA = sbase + (uint32_t)((slot * STG_E) * 2);
        const uint32_t stB = stA + (uint32_t)(STG_A * 2);
#pragma unroll
        for (int kk = 0; kk < 64; kk += 16) {
            uint32_t a[4][4];
#pragma unroll
            for (int mi = 0; mi < 4; mi++)
                ldsm_x4(a[mi][0], a[mi][1], a[mi][2], a[mi][3],
                        stA + (uint32_t)(((aRow + mi * 16) * MLDA + kk + aColH) * 2));
            uint32_t b[4][2];
#pragma unroll
            for (int ni = 0; ni < 2; ni++) {
                uint32_t r0, r1, r2, r3;
                ldsm_x4(r0, r1, r2, r3,
                        stB + (uint32_t)(((bRow + ni * 16) * MLDA + kk + bColH) * 2));
                b[ni * 2][0] = r0; b[ni * 2][1] = r1;
                b[ni * 2 + 1][0] = r2; b[ni * 2 + 1][1] = r3;
            }
#pragma unroll
            for (int mi = 0; mi < 4; mi++)
#pragma unroll
                for (int nj = 0; nj < 4; nj++)
                    mma16816(d[mi][nj], a[mi], b[nj]);
        }
        if (++slot == 3) slot = 0;
    }

    const int rb = m0 + wm * 64 + (lane >> 2);
    const int cb = n0 + wn * 32 + ((lane & 3) << 1);
#pragma unroll
    for (int mi = 0; mi < 4; mi++) {
#pragma unroll
        for (int nj = 0; nj < 4; nj++) {
            const int c = cb + nj * 8;
            const float2 bv = *(const float2*)(bias + c);
#pragma unroll
            for (int h = 0; h < 2; h++) {
                const int r = rb + mi * 16 + h * 8;
                const float v0 = d[mi][nj][h * 2]     + bv.x;
                const float v1 = d[mi][nj][h * 2 + 1] + bv.y;
                if (EPI == 0) {
                    __nv_bfloat162 o = __floats2bfloat162_rn(v0, v1);
                    *(__nv_bfloat162*)((__nv_bfloat16*)Cp + (size_t)r * N + c) = o;
                } else if (EPI == 4) {
                    int b_ = r >> 12, pos = r & 4095;
                    int hh = pos >> 6, ww = pos & 63;
                    int hs = (hh - CSS) & 63, ws = (ww - CSS) & 63;
                    int m = (b_ << 12) + ((((hs >> 3) << 3) + (ws >> 3)) << 6)
                            + ((hs & 7) << 3) + (ws & 7);
                    size_t off = (size_t)r * N + c;
                    float2 xv = *(const float2*)(resid + off);
                    __nv_bfloat162 pv = *(const __nv_bfloat162*)(proj2 + (size_t)m * 256 + c);
                    float2 pf = __bfloat1622float2(pv);
                    float2 o = {v0 + xv.x + pf.x, v1 + xv.y + pf.y};
                    *(float2*)((float*)Cp + off) = o;
                } else {  // EPI == 3
                    float sg = v0 / (1.f + __expf(-v0));
                    ((__nv_bfloat16*)Cp)[(size_t)r * (N >> 1) + (c >> 1)] =
                        __float2bfloat16(sg * v1);
                }
            }
        }
    }
}

// ---------------- LN1 + cyclic shift + window partition ----------------
__global__ void k_ln1_shift(const float* __restrict__ x, const float* __restrict__ w,
                            const float* __restrict__ bb, __nv_bfloat16* __restrict__ out) {
    int gw = (blockIdx.x * blockDim.x + threadIdx.x) >> 5;
    int lane = threadIdx.x & 31;
    if (gw >= MTOK) return;
    int b = gw >> 12, r = gw & 4095;
    int wi = r >> 6, n = r & 63;
    int hs = ((wi >> 3) << 3) + (n >> 3);
    int ws = ((wi & 7) << 3) + (n & 7);
    int h0 = (hs + CSS) & 63, w0 = (ws + CSS) & 63;
    const float4* row = (const float4*)(x + ((size_t)(b << 12) + (h0 << 6) + w0) * CC);
    float4 a = row[lane * 2], c = row[lane * 2 + 1];
    float s  = a.x + a.y + a.z + a.w + c.x + c.y + c.z + c.w;
    float sq = a.x*a.x + a.y*a.y + a.z*a.z + a.w*a.w + c.x*c.x + c.y*c.y + c.z*c.z + c.w*c.w;
    s = warp_sum(s); sq = warp_sum(sq);
    float mean = s * (1.f / 256.f);
    float var  = sq * (1.f / 256.f) - mean * mean;
    float rs   = rsqrtf(var + 1e-5f);
    const float4* wp = (const float4*)w;
    const float4* bp = (const float4*)bb;
    float4 w0v = wp[lane * 2], w1v = wp[lane * 2 + 1];
    float4 b0v = bp[lane * 2], b1v = bp[lane * 2 + 1];
    __align__(16) __nv_bfloat16 o8[8];
    o8[0] = __float2bfloat16((a.x - mean) * rs * w0v.x + b0v.x);
    o8[1] = __float2bfloat16((a.y - mean) * rs * w0v.y + b0v.y);
    o8[2] = __float2bfloat16((a.z - mean) * rs * w0v.z + b0v.z);
    o8[3] = __float2bfloat16((a.w - mean) * rs * w0v.w + b0v.w);
    o8[4] = __float2bfloat16((c.x - mean) * rs * w1v.x + b1v.x);
    o8[5] = __float2bfloat16((c.y - mean) * rs * w1v.y + b1v.y);
    o8[6] = __float2bfloat16((c.z - mean) * rs * w1v.z + b1v.z);
    o8[7] = __float2bfloat16((c.w - mean) * rs * w1v.w + b1v.w);
    *(uint4*)(out + (size_t)gw * CC + lane * 8) = *(const uint4*)o8;
}

// ---------------- tensor-core attention: 4 heads per CTA (2 CTAs per window) ----------------
// 256 thr, 8 warps: h_local = warp>>1 (0..3), rh = warp&1 (row half).
// smem stages Q|K|V for this CTA's 4 heads only: 64 x 384 bf16 (stride 392) -> 2 CTAs/SM.
constexpr int AT2_STRIDE = 392;                       // 384 + 8 pad (784B rows, odd x16B)
constexpr int AT2_TILE_B = 64 * AT2_STRIDE * 2;       // 50176
constexpr int AT2_SMEM   = AT2_TILE_B + 1800 * 4;     // + rpb copy [225][8] f32

__global__ void __launch_bounds__(256, 2)
k_attn2(const __nv_bfloat16* __restrict__ qkv, const float* __restrict__ rpb,
        __nv_bfloat16* __restrict__ out) {
    extern __shared__ __align__(16) char asmem[];
    const uint32_t sb = (uint32_t)__cvta_generic_to_shared(asmem);
    const float* bias_sm = (const float*)(asmem + AT2_TILE_B);
    const int win   = blockIdx.x >> 1;
    const int hbase = (blockIdx.x & 1) << 2;
    const int tid  = threadIdx.x;
    const int lane = tid & 31;
    const int warp = tid >> 5;
    const int hl   = warp >> 1;          // local head 0..3
    const int h    = hbase + hl;         // global head
    const int rh   = warp & 1;
    const int rbase = rh * 32;

    // stage Q|K|V columns for heads hbase..hbase+3 (64 rows x 384 cols) + bias table
    {
        const __nv_bfloat16* src = qkv + (size_t)win * 64 * 768;
        for (int i = tid; i < 3072; i += 256) {
            int row = i / 48;
            int c8  = (i % 48) << 3;           // dst col 0..383
            int seg = c8 >> 7;                 // 0=q,1=k,2=v
            int cin = c8 & 127;
            int gcol = seg * 256 + hbase * 32 + cin;
            cp_async16(sb + (uint32_t)((row * AT2_STRIDE + c8) * 2),
                       src + (size_t)row * 768 + gcol);
        }
        uint32_t bb = sb + AT2_TILE_B;
        for (int i = tid; i < 450; i += 256)
            cp_async16(bb + (uint32_t)(i * 16), rpb + i * 4);
    }
    CP_COMMIT();
    CP_WAIT0();
    __syncthreads();

    const int qcol = hl * 32, kcol = 128 + hl * 32, vcol = 256 + hl * 32;

    // ---- S = Q @ K^T  (32 rows x 64 cols per warp) ----
    float s[2][8][4];
#pragma unroll
    for (int mi = 0; mi < 2; mi++)
#pragma unroll
        for (int nj = 0; nj < 8; nj++)
#pragma unroll
            for (int e = 0; e < 4; e++) s[mi][nj][e] = 0.f;

#pragma unroll
    for (int ks = 0; ks < 32; ks += 16) {
        uint32_t a[2][4];
#pragma unroll
        for (int mi = 0; mi < 2; mi++)
            ldsm_x4(a[mi][0], a[mi][1], a[mi][2], a[mi][3],
                    sb + (uint32_t)(((rbase + mi * 16 + (lane & 15)) * AT2_STRIDE
                                     + qcol + ks + ((lane >> 4) << 3)) * 2));
        uint32_t b[8][2];
#pragma unroll
        for (int ni = 0; ni < 4; ni++) {
            uint32_t r0, r1, r2, r3;
            ldsm_x4(r0, r1, r2, r3,
                    sb + (uint32_t)(((ni * 16 + (lane & 7) + ((lane >> 4) << 3)) * AT2_STRIDE
                                     + kcol + ks + (((lane >> 3) & 1) << 3)) * 2));
            b[ni * 2][0] = r0; b[ni * 2][1] = r1;
            b[ni * 2 + 1][0] = r2; b[ni * 2 + 1][1] = r3;
        }
#pragma unroll
        for (int mi = 0; mi < 2; mi++)
#pragma unroll
            for (int nj = 0; nj < 8; nj++)
                mma16816(s[mi][nj], a[mi], b[nj]);
    }

    // ---- scale + bias + shift-mask, row max ----
    const int wi = win & 63;
    const int wr = (wi >> 3) << 3, wc = (wi & 7) << 3;
    const float scale = 0.17677669529663687f;
    float mx[2][2] = {{-1e30f,-1e30f},{-1e30f,-1e30f}};
#pragma unroll
    for (int mi = 0; mi < 2; mi++)
#pragma unroll
        for (int h8 = 0; h8 < 2; h8++) {
            int qi = rbase + mi * 16 + (lane >> 2) + h8 * 8;
            int qri = qi >> 3, qci = qi & 7;
            int myid = reg3(wr + qri) * 3 + reg3(wc + qci);
#pragma unroll
            for (int nj = 0; nj < 8; nj++)
#pragma unroll
                for (int e = 0; e < 2; e++) {
                    int kj = nj * 8 + ((lane & 3) << 1) + e;
                    int krj = kj >> 3, kcj = kj & 7;
                    float v = fmaf(s[mi][nj][h8 * 2 + e], scale,
                                   bias_sm[(((qri - krj + 7) * 15 + qci - kcj + 7) << 3) + h]);
                    int jid = reg3(wr + krj) * 3 + reg3(wc + kcj);
                    if (jid != myid) v -= 100.f;
                    s[mi][nj][h8 * 2 + e] = v;
                    mx[mi][h8] = fmaxf(mx[mi][h8], v);
                }
        }
#pragma unroll
    for (int mi = 0; mi < 2; mi++)
#pragma unroll
        for (int h8 = 0; h8 < 2; h8++) {
            mx[mi][h8] = fmaxf(mx[mi][h8], __shfl_xor_sync(0xffffffffu, mx[mi][h8], 1));
            mx[mi][h8] = fmaxf(mx[mi][h8], __shfl_xor_sync(0xffffffffu, mx[mi][h8], 2));
        }

    // ---- exp + row sum ----
    float sum[2][2] = {{0,0},{0,0}};
#pragma unroll
    for (int mi = 0; mi < 2; mi++)
#pragma unroll
        for (int nj = 0; nj < 8; nj++)
#pragma unroll
            for (int e4 = 0; e4 < 4; e4++) {
                int h8 = e4 >> 1;
                float v = __expf(s[mi][nj][e4] - mx[mi][h8]);
                s[mi][nj][e4] = v;
                sum[mi][h8] += v;
            }
    float inv[2][2];
#pragma unroll
    for (int mi = 0; mi < 2; mi++)
#pragma unroll
        for (int h8 = 0; h8 < 2; h8++) {
            float t = sum[mi][h8];
            t += __shfl_xor_sync(0xffffffffu, t, 1);
            t += __shfl_xor_sync(0xffffffffu, t, 2);
            inv[mi][h8] = __frcp_rn(t);
        }

    // ---- pack P (accum layout == A-frag layout) ----
    uint32_t p[2][4][4];
#pragma unroll
    for (int mi = 0; mi < 2; mi++)
#pragma unroll
        for (int ks = 0; ks < 4; ks++) {
            p[mi][ks][0] = bf2_to_u32(s[mi][2*ks][0],   s[mi][2*ks][1]);
            p[mi][ks][1] = bf2_to_u32(s[mi][2*ks][2],   s[mi][2*ks][3]);
            p[mi][ks][2] = bf2_to_u32(s[mi][2*ks+1][0], s[mi][2*ks+1][1]);
            p[mi][ks][3] = bf2_to_u32(s[mi][2*ks+1][2], s[mi][2*ks+1][3]);
        }

    // ---- O = P @ V ----
    float o[2][4][4];
#pragma unroll
    for (int mi = 0; mi < 2; mi++)
#pragma unroll
        for (int dj = 0; dj < 4; dj++)
#pragma unroll
            for (int e = 0; e < 4; e++) o[mi][dj][e] = 0.f;

#pragma unroll
    for (int ks = 0; ks < 4; ks++) {
        uint32_t vb[4][2];
#pragma unroll
        for (int dt = 0; dt < 2; dt++) {
            uint32_t r0, r1, r2, r3;
            ldsm_x4_trans(r0, r1, r2, r3,
                sb + (uint32_t)(((ks * 16 + (lane & 7) + (((lane >> 3) & 1) << 3)) * AT2_STRIDE
                                 + vcol + dt * 16 + ((lane >> 4) << 3)) * 2));
            vb[dt * 2][0] = r0; vb[dt * 2][1] = r1;
            vb[dt * 2 + 1][0] = r2; vb[dt * 2 + 1][1] = r3;
        }
#pragma unroll
        for (int mi = 0; mi < 2; mi++)
#pragma unroll
            for (int dj = 0; dj < 4; dj++)
                mma16816(o[mi][dj], p[mi][ks], vb[dj]);
    }

    // ---- normalize + store ----
#pragma unroll
    for (int mi = 0; mi < 2; mi++)
#pragma unroll
        for (int dj = 0; dj < 4; dj++)
#pragma unroll
            for (int h8 = 0; h8 < 2; h8++) {
                int row = rbase + mi * 16 + (lane >> 2) + h8 * 8;
                int col = dj * 8 + ((lane & 3) << 1);
                __nv_bfloat162 ov = __floats2bfloat162_rn(
                    o[mi][dj][h8 * 2]     * inv[mi][h8],
                    o[mi][dj][h8 * 2 + 1] * inv[mi][h8]);
                *(__nv_bfloat162*)(out + (size_t)(win * 64 + row) * 256 + h * 32 + col) = ov;
            }
}

// ---------------- residual (window-reverse + unshift) + LN2 ----------------
__global__ void k_resid_ln2(const float* __restrict__ x, const __nv_bfloat16* __restrict__ proj,
                            const float* __restrict__ w, const float* __restrict__ bb,
                            __nv_bfloat16* __restrict__ ln2) {
    int gw = (blockIdx.x * blockDim.x + threadIdx.x) >> 5;
    int lane = threadIdx.x & 31;
    if (gw >= MTOK) return;
    int b = gw >> 12, pos = gw & 4095;
    int hh = pos >> 6, ww = pos & 63;
    int hs = (hh - CSS) & 63, ws = (ww - CSS) & 63;
    int m = (b << 12) + ((((hs >> 3) << 3) + (ws >> 3)) << 6) + ((hs & 7) << 3) + (ws & 7);
    const float4* xr = (const float4*)(x + (size_t)gw * CC);
    float4 a = xr[lane * 2], c = xr[lane * 2 + 1];
    uint4 pu = *(const uint4*)(proj + (size_t)m * CC + lane * 8);
    const __nv_bfloat162* p2 = (const __nv_bfloat162*)&pu;
    float2 f0 = __bfloat1622float2(p2[0]);
    float2 f1 = __bfloat1622float2(p2[1]);
    float2 f2 = __bfloat1622float2(p2[2]);
    float2 f3 = __bfloat1622float2(p2[3]);
    a.x += f0.x; a.y += f0.y; a.z += f1.x; a.w += f1.y;
    c.x += f2.x; c.y += f2.y; c.z += f3.x; c.w += f3.y;
    float s  = a.x + a.y + a.z + a.w + c.x + c.y + c.z + c.w;
    float sq = a.x*a.x + a.y*a.y + a.z*a.z + a.w*a.w + c.x*c.x + c.y*c.y + c.z*c.z + c.w*c.w;
    s = warp_sum(s); sq = warp_sum(sq);
    float mean = s * (1.f / 256.f);
    float var  = sq * (1.f / 256.f) - mean * mean;
    float rs   = rsqrtf(var + 1e-5f);
    const float4* wp = (const float4*)w;
    const float4* bp = (const float4*)bb;
    float4 w0v = wp[lane * 2], w1v = wp[lane * 2 + 1];
    float4 b0v = bp[lane * 2], b1v = bp[lane * 2 + 1];
    __align__(16) __nv_bfloat16 o8[8];
    o8[0] = __float2bfloat16((a.x - mean) * rs * w0v.x + b0v.x);
    o8[1] = __float2bfloat16((a.y - mean) * rs * w0v.y + b0v.y);
    o8[2] = __float2bfloat16((a.z - mean) * rs * w0v.z + b0v.z);
    o8[3] = __float2bfloat16((a.w - mean) * rs * w0v.w + b0v.w);
    o8[4] = __float2bfloat16((c.x - mean) * rs * w1v.x + b1v.x);
    o8[5] = __float2bfloat16((c.y - mean) * rs * w1v.y + b1v.y);
    o8[6] = __float2bfloat16((c.z - mean) * rs * w1v.z + b1v.z);
    o8[7] = __float2bfloat16((c.w - mean) * rs * w1v.w + b1v.w);
    *(uint4*)(ln2 + (size_t)gw * CC + lane * 8) = *(const uint4*)o8;
}

// ---------------- launcher ----------------
extern "C" void kernel_launch(void* const* d_in, const int* in_sizes, int n_in,
                              void* d_out, int out_size) {
    const float* x     = (const float*)d_in[0];
    const float* n1w   = (const float*)d_in[1];
    const float* n1b   = (const float*)d_in[2];
    const float* qkvw  = (const float*)d_in[3];
    const float* qkvb  = (const float*)d_in[4];
    const float* projw = (const float*)d_in[5];
    const float* projb = (const float*)d_in[6];
    const float* rpb   = (const float*)d_in[7];
    const float* n2w   = (const float*)d_in[8];
    const float* n2b   = (const float*)d_in[9];
    const float* f12w  = (const float*)d_in[10];
    const float* f12b  = (const float*)d_in[11];
    const float* f2w   = (const float*)d_in[12];
    const float* f2b   = (const float*)d_in[13];
    float* out = (float*)d_out;

    void *p_hw, *p_qkv, *p_att, *p_proj, *p_ln2, *p_gat;
    void *p_wq, *p_wp, *p_w12, *p_b12, *p_w2;
    cudaGetSymbolAddress(&p_hw, g_hw);
    cudaGetSymbolAddress(&p_qkv, g_qkv);
    cudaGetSymbolAddress(&p_att, g_att);
    cudaGetSymbolAddress(&p_proj, g_proj);
    cudaGetSymbolAddress(&p_ln2, g_ln2);
    cudaGetSymbolAddress(&p_gat, g_gat);
    cudaGetSymbolAddress(&p_wq, g_wqkv);
    cudaGetSymbolAddress(&p_wp, g_wproj);
    cudaGetSymbolAddress(&p_w12, g_wf12r);
    cudaGetSymbolAddress(&p_b12, g_b12r);
    cudaGetSymbolAddress(&p_w2, g_wf2);

    cudaFuncSetAttribute(k_gemm3<0>, cudaFuncAttributeMaxDynamicSharedMemorySize, M3_SMEM);
    cudaFuncSetAttribute(k_gemm3<3>, cudaFuncAttributeMaxDynamicSharedMemorySize, M3_SMEM);
    cudaFuncSetAttribute(k_gemm3<4>, cudaFuncAttributeMaxDynamicSharedMemorySize, M3_SMEM);
    cudaFuncSetAttribute(k_attn2,    cudaFuncAttributeMaxDynamicSharedMemorySize, AT2_SMEM);

    // one prep launch for all weights
    k_prep<<<2048, 256>>>(qkvw, projw, f2w, f12w, f12b,
                          (__nv_bfloat16*)p_wq, (__nv_bfloat16*)p_wp,
                          (__nv_bfloat16*)p_w2, (__nv_bfloat16*)p_w12, (float*)p_b12);

    // LN1 + shift + window partition
    k_ln1_shift<<<16384, 256>>>(x, n1w, n1b, (__nv_bfloat16*)p_hw);

    // qkv: [131072,256] @ [768,256]^T -> bf16
    k_gemm3<0><<<dim3(6, MTOK / 128), 256, M3_SMEM>>>(
        (const __nv_bfloat16*)p_hw, (const __nv_bfloat16*)p_wq, qkvb,
        p_qkv, nullptr, nullptr, MTOK, 768, 256);

    // tensor-core windowed attention (4 heads per CTA, 2 CTAs per window, 2 CTAs/SM)
    k_attn2<<<4096, 256, AT2_SMEM>>>((const __nv_bfloat16*)p_qkv, rpb,
                                     (__nv_bfloat16*)p_att);

    // proj -> bf16 (window order)
    k_gemm3<0><<<dim3(2, MTOK / 128), 256, M3_SMEM>>>(
        (const __nv_bfloat16*)p_att, (const __nv_bfloat16*)p_wp, projb,
        p_proj, nullptr, nullptr, MTOK, 256, 256);

    // residual (window reverse + unshift) + LN2
    k_resid_ln2<<<16384, 256>>>(x, (const __nv_bfloat16*)p_proj, n2w, n2b,
                                (__nv_bfloat16*)p_ln2);

    // fc12 (fused SiLU gate): [131072,256] @ [2048,256]^T -> [131072,1024] bf16
    k_gemm3<3><<<dim3(16, MTOK / 128), 256, M3_SMEM>>>(
        (const __nv_bfloat16*)p_ln2, (const __nv_bfloat16*)p_w12, (const float*)p_b12,
        p_gat, nullptr, nullptr, MTOK, 2048, 256);

    // fc2 + recomputed residual (x + proj) -> d_out fp32
    k_gemm3<4><<<dim3(2, MTOK / 128), 256, M3_SMEM>>>(
        (const __nv_bfloat16*)p_gat, (const __nv_bfloat16*)p_w2, f2b,
        out, x, (const __nv_bfloat16*)p_proj, MTOK, 256, 1024);
}

// round 17
// speedup vs baseline: 1.0905x; 1.0035x over previous
#include <cuda_runtime.h>
#include <cuda_bf16.h>
#include <cstdint>

// ---------------- problem constants ----------------
constexpr int CC    = 256;
constexpr int CSS   = 4;
constexpr int CHID  = 1024;
constexpr int MTOK  = 32 * 64 * 64;  // 131072 tokens

// ---------------- device scratch ----------------
__device__ __nv_bfloat16 g_hw  [(size_t)MTOK * CC];
__device__ __nv_bfloat16 g_qkv [(size_t)MTOK * 3 * CC];
__device__ __nv_bfloat16 g_att [(size_t)MTOK * CC];
__device__ __nv_bfloat16 g_proj[(size_t)MTOK * CC];
__device__ __nv_bfloat16 g_ln2 [(size_t)MTOK * CC];
__device__ __nv_bfloat16 g_gat [(size_t)MTOK * CHID];
__device__ __nv_bfloat16 g_wqkv [3 * CC * CC];
__device__ __nv_bfloat16 g_wproj[CC * CC];
__device__ __nv_bfloat16 g_wf12r[2 * CHID * CC];
__device__ float         g_b12r [2 * CHID];
__device__ __nv_bfloat16 g_wf2  [CC * CHID];

// ---------------- helpers ----------------
__device__ __forceinline__ float warp_sum(float v) {
#pragma unroll
    for (int o = 16; o > 0; o >>= 1) v += __shfl_xor_sync(0xffffffffu, v, o);
    return v;
}
__device__ __forceinline__ int reg3(int p) { return p < 56 ? 0 : (p < 60 ? 1 : 2); }

__device__ __forceinline__ uint32_t bf2_to_u32(float lo, float hi) {
    union { __nv_bfloat162 b; uint32_t u; } cvt;
    cvt.b = __floats2bfloat162_rn(lo, hi);
    return cvt.u;
}

__device__ __forceinline__ void cp_async16(uint32_t smem_dst, const void* gmem_src) {
    asm volatile("cp.async.cg.shared.global [%0], [%1], 16;\n" :: "r"(smem_dst), "l"(gmem_src));
}
#define CP_COMMIT() asm volatile("cp.async.commit_group;\n" ::: "memory")
#define CP_WAIT1()  asm volatile("cp.async.wait_group 1;\n" ::: "memory")
#define CP_WAIT0()  asm volatile("cp.async.wait_group 0;\n" ::: "memory")

__device__ __forceinline__ void ldsm_x4(uint32_t& r0, uint32_t& r1, uint32_t& r2, uint32_t& r3,
                                        uint32_t addr) {
    asm volatile("ldmatrix.sync.aligned.m8n8.x4.shared.b16 {%0,%1,%2,%3}, [%4];"
                 : "=r"(r0), "=r"(r1), "=r"(r2), "=r"(r3) : "r"(addr));
}
__device__ __forceinline__ void ldsm_x4_trans(uint32_t& r0, uint32_t& r1, uint32_t& r2, uint32_t& r3,
                                              uint32_t addr) {
    asm volatile("ldmatrix.sync.aligned.m8n8.x4.trans.shared.b16 {%0,%1,%2,%3}, [%4];"
                 : "=r"(r0), "=r"(r1), "=r"(r2), "=r"(r3) : "r"(addr));
}
__device__ __forceinline__ void mma16816(float* d, const uint32_t* a, const uint32_t* b) {
    asm volatile(
        "mma.sync.aligned.m16n8k16.row.col.f32.bf16.bf16.f32 "
        "{%0,%1,%2,%3}, {%4,%5,%6,%7}, {%8,%9}, {%0,%1,%2,%3};"
        : "+f"(d[0]), "+f"(d[1]), "+f"(d[2]), "+f"(d[3])
        : "r"(a[0]), "r"(a[1]), "r"(a[2]), "r"(a[3]), "r"(b[0]), "r"(b[1]));
}

// ---------------- unified weight prep (one launch) ----------------
__global__ void k_prep(const float* __restrict__ qkvw, const float* __restrict__ projw,
                       const float* __restrict__ f2w, const float* __restrict__ f12w,
                       const float* __restrict__ f12b,
                       __nv_bfloat16* __restrict__ wq, __nv_bfloat16* __restrict__ wp,
                       __nv_bfloat16* __restrict__ w2, __nv_bfloat16* __restrict__ w12r,
                       float* __restrict__ b12r) {
    int i = blockIdx.x * blockDim.x + threadIdx.x;
    if (i < 524288) {
        int r = i >> 8, c = i & 255;
        int src = (r & 1) ? (r >> 1) + 1024 : (r >> 1);
        w12r[i] = __float2bfloat16(f12w[src * 256 + c]);
    }
    if (i < 262144) w2[i] = __float2bfloat16(f2w[i]);
    if (i < 196608) wq[i] = __float2bfloat16(qkvw[i]);
    if (i < 65536)  wp[i] = __float2bfloat16(projw[i]);
    if (i < 2048) {
        int src = (i & 1) ? (i >> 1) + 1024 : (i >> 1);
        b12r[i] = f12b[src];
    }
}

// ---------------- mma.sync GEMM: BK=64, 3 stages, 2 CTAs/SM (R14 — validated) ----------------
constexpr int MLDA  = 72;
constexpr int STG_A = 128 * MLDA;
constexpr int STG_B = 128 * MLDA;
constexpr int STG_E = STG_A + STG_B;
constexpr int M3_SMEM = 3 * STG_E * 2;         // 110592 bytes (2 CTAs/SM)

__device__ __forceinline__ void m3_stage_load(
    const __nv_bfloat16* __restrict__ A, const __nv_bfloat16* __restrict__ W,
    uint32_t sbase, int slot, int k0, int m0, int n0, int K, int tid) {
    uint32_t st = sbase + (uint32_t)(slot * STG_E * 2);
#pragma unroll
    for (int u = 0; u < 4; u++) {
        int ch = tid + (u << 8);
        int row = ch >> 3, c = (ch & 7) << 3;
        cp_async16(st + (uint32_t)((row * MLDA + c) * 2),
                   A + (size_t)(m0 + row) * K + k0 + c);
    }
    uint32_t stb = st + STG_A * 2;
#pragma unroll
    for (int u = 0; u < 4; u++) {
        int ch = tid + (u << 8);
        int row = ch >> 3, c = (ch & 7) << 3;
        cp_async16(stb + (uint32_t)((row * MLDA + c) * 2),
                   W + (size_t)(n0 + row) * K + k0 + c);
    }
}

template <int EPI>
__global__ void __launch_bounds__(256, 2)
k_gemm3(const __nv_bfloat16* __restrict__ A, const __nv_bfloat16* __restrict__ W,
        const float* __restrict__ bias, void* __restrict__ Cp,
        const float* __restrict__ resid, const __nv_bfloat16* __restrict__ proj2,
        int M, int N, int K) {
    extern __shared__ __align__(16) char dsm[];
    const uint32_t sbase = (uint32_t)__cvta_generic_to_shared(dsm);

    const int tid  = threadIdx.x;
    const int lane = tid & 31;
    const int warp = tid >> 5;
    const int wm   = warp >> 2;
    const int wn   = warp & 3;
    const int m0 = blockIdx.y << 7;
    const int n0 = blockIdx.x << 7;
    const int KT = K >> 6;

    const int aRow  = wm * 64 + (lane & 15);
    const int aColH = (lane >> 4) << 3;
    const int bRow  = wn * 32 + (lane & 7) + ((lane >> 4) << 3);
    const int bColH = ((lane >> 3) & 1) << 3;

    float d[4][4][4];
#pragma unroll
    for (int i = 0; i < 4; i++)
#pragma unroll
        for (int j = 0; j < 4; j++)
#pragma unroll
            for (int e = 0; e < 4; e++) d[i][j][e] = 0.f;

#pragma unroll
    for (int s = 0; s < 2; s++) {
        m3_stage_load(A, W, sbase, s, s << 6, m0, n0, K, tid);
        CP_COMMIT();
    }

    int slot = 0;
    for (int kt = 0; kt < KT; kt++) {
        CP_WAIT1();
        __syncthreads();
        if (kt + 2 < KT) {
            int ns = slot + 2; if (ns >= 3) ns -= 3;
            m3_stage_load(A, W, sbase, ns, (kt + 2) << 6, m0, n0, K, tid);
        }
        CP_COMMIT();

        const uint32_t stA = sbase + (uint32_t)((slot * STG_E) * 2);
        const uint32_t stB = stA + (uint32_t)(STG_A * 2);
#pragma unroll
        for (int kk = 0; kk < 64; kk += 16) {
            uint32_t a[4][4];
#pragma unroll
            for (int mi = 0; mi < 4; mi++)
                ldsm_x4(a[mi][0], a[mi][1], a[mi][2], a[mi][3],
                        stA + (uint32_t)(((aRow + mi * 16) * MLDA + kk + aColH) * 2));
            uint32_t b[4][2];
#pragma unroll
            for (int ni = 0; ni < 2; ni++) {
                uint32_t r0, r1, r2, r3;
                ldsm_x4(r0, r1, r2, r3,
                        stB + (uint32_t)(((bRow + ni * 16) * MLDA + kk + bColH) * 2));
                b[ni * 2][0] = r0; b[ni * 2][1] = r1;
                b[ni * 2 + 1][0] = r2; b[ni * 2 + 1][1] = r3;
            }
#pragma unroll
            for (int mi = 0; mi < 4; mi++)
#pragma unroll
                for (int nj = 0; nj < 4; nj++)
                    mma16816(d[mi][nj], a[mi], b[nj]);
        }
        if (++slot == 3) slot = 0;
    }

    const int rb = m0 + wm * 64 + (lane >> 2);
    const int cb = n0 + wn * 32 + ((lane & 3) << 1);
#pragma unroll
    for (int mi = 0; mi < 4; mi++) {
#pragma unroll
        for (int nj = 0; nj < 4; nj++) {
            const int c = cb + nj * 8;
            const float2 bv = *(const float2*)(bias + c);
#pragma unroll
            for (int h = 0; h < 2; h++) {
                const int r = rb + mi * 16 + h * 8;
                const float v0 = d[mi][nj][h * 2]     + bv.x;
                const float v1 = d[mi][nj][h * 2 + 1] + bv.y;
                if (EPI == 0) {
                    __nv_bfloat162 o = __floats2bfloat162_rn(v0, v1);
                    *(__nv_bfloat162*)((__nv_bfloat16*)Cp + (size_t)r * N + c) = o;
                } else if (EPI == 4) {
                    int b_ = r >> 12, pos = r & 4095;
                    int hh = pos >> 6, ww = pos & 63;
                    int hs = (hh - CSS) & 63, ws = (ww - CSS) & 63;
                    int m = (b_ << 12) + ((((hs >> 3) << 3) + (ws >> 3)) << 6)
                            + ((hs & 7) << 3) + (ws & 7);
                    size_t off = (size_t)r * N + c;
                    float2 xv = *(const float2*)(resid + off);
                    __nv_bfloat162 pv = *(const __nv_bfloat162*)(proj2 + (size_t)m * 256 + c);
                    float2 pf = __bfloat1622float2(pv);
                    float2 o = {v0 + xv.x + pf.x, v1 + xv.y + pf.y};
                    *(float2*)((float*)Cp + off) = o;
                } else {  // EPI == 3
                    float sg = v0 / (1.f + __expf(-v0));
                    ((__nv_bfloat16*)Cp)[(size_t)r * (N >> 1) + (c >> 1)] =
                        __float2bfloat16(sg * v1);
                }
            }
        }
    }
}

// ---------------- LN1 + cyclic shift + window partition ----------------
__global__ void k_ln1_shift(const float* __restrict__ x, const float* __restrict__ w,
                            const float* __restrict__ bb, __nv_bfloat16* __restrict__ out) {
    int gw = (blockIdx.x * blockDim.x + threadIdx.x) >> 5;
    int lane = threadIdx.x & 31;
    if (gw >= MTOK) return;
    int b = gw >> 12, r = gw & 4095;
    int wi = r >> 6, n = r & 63;
    int hs = ((wi >> 3) << 3) + (n >> 3);
    int ws = ((wi & 7) << 3) + (n & 7);
    int h0 = (hs + CSS) & 63, w0 = (ws + CSS) & 63;
    const float4* row = (const float4*)(x + ((size_t)(b << 12) + (h0 << 6) + w0) * CC);
    float4 a = row[lane * 2], c = row[lane * 2 + 1];
    float s  = a.x + a.y + a.z + a.w + c.x + c.y + c.z + c.w;
    float sq = a.x*a.x + a.y*a.y + a.z*a.z + a.w*a.w + c.x*c.x + c.y*c.y + c.z*c.z + c.w*c.w;
    s = warp_sum(s); sq = warp_sum(sq);
    float mean = s * (1.f / 256.f);
    float var  = sq * (1.f / 256.f) - mean * mean;
    float rs   = rsqrtf(var + 1e-5f);
    const float4* wp = (const float4*)w;
    const float4* bp = (const float4*)bb;
    float4 w0v = wp[lane * 2], w1v = wp[lane * 2 + 1];
    float4 b0v = bp[lane * 2], b1v = bp[lane * 2 + 1];
    __align__(16) __nv_bfloat16 o8[8];
    o8[0] = __float2bfloat16((a.x - mean) * rs * w0v.x + b0v.x);
    o8[1] = __float2bfloat16((a.y - mean) * rs * w0v.y + b0v.y);
    o8[2] = __float2bfloat16((a.z - mean) * rs * w0v.z + b0v.z);
    o8[3] = __float2bfloat16((a.w - mean) * rs * w0v.w + b0v.w);
    o8[4] = __float2bfloat16((c.x - mean) * rs * w1v.x + b1v.x);
    o8[5] = __float2bfloat16((c.y - mean) * rs * w1v.y + b1v.y);
    o8[6] = __float2bfloat16((c.z - mean) * rs * w1v.z + b1v.z);
    o8[7] = __float2bfloat16((c.w - mean) * rs * w1v.w + b1v.w);
    *(uint4*)(out + (size_t)gw * CC + lane * 8) = *(const uint4*)o8;
}

// ---------------- tensor-core attention: 4 heads per CTA (2 CTAs per window) ----------------
// Interior windows (wr<=48 && wc<=48) have identically-zero shift mask: slim path.
constexpr int AT2_STRIDE = 392;
constexpr int AT2_TILE_B = 64 * AT2_STRIDE * 2;       // 50176
constexpr int AT2_SMEM   = AT2_TILE_B + 1800 * 4;

__global__ void __launch_bounds__(256, 2)
k_attn2(const __nv_bfloat16* __restrict__ qkv, const float* __restrict__ rpb,
        __nv_bfloat16* __restrict__ out) {
    extern __shared__ __align__(16) char asmem[];
    const uint32_t sb = (uint32_t)__cvta_generic_to_shared(asmem);
    const float* bias_sm = (const float*)(asmem + AT2_TILE_B);
    const int win   = blockIdx.x >> 1;
    const int hbase = (blockIdx.x & 1) << 2;
    const int tid  = threadIdx.x;
    const int lane = tid & 31;
    const int warp = tid >> 5;
    const int hl   = warp >> 1;
    const int h    = hbase + hl;
    const int rh   = warp & 1;
    const int rbase = rh * 32;

    {
        const __nv_bfloat16* src = qkv + (size_t)win * 64 * 768;
        for (int i = tid; i < 3072; i += 256) {
            int row = i / 48;
            int c8  = (i % 48) << 3;
            int seg = c8 >> 7;
            int cin = c8 & 127;
            int gcol = seg * 256 + hbase * 32 + cin;
            cp_async16(sb + (uint32_t)((row * AT2_STRIDE + c8) * 2),
                       src + (size_t)row * 768 + gcol);
        }
        uint32_t bb = sb + AT2_TILE_B;
        for (int i = tid; i < 450; i += 256)
            cp_async16(bb + (uint32_t)(i * 16), rpb + i * 4);
    }
    CP_COMMIT();
    CP_WAIT0();
    __syncthreads();

    const int qcol = hl * 32, kcol = 128 + hl * 32, vcol = 256 + hl * 32;

    // ---- S = Q @ K^T ----
    float s[2][8][4];
#pragma unroll
    for (int mi = 0; mi < 2; mi++)
#pragma unroll
        for (int nj = 0; nj < 8; nj++)
#pragma unroll
            for (int e = 0; e < 4; e++) s[mi][nj][e] = 0.f;

#pragma unroll
    for (int ks = 0; ks < 32; ks += 16) {
        uint32_t a[2][4];
#pragma unroll
        for (int mi = 0; mi < 2; mi++)
            ldsm_x4(a[mi][0], a[mi][1], a[mi][2], a[mi][3],
                    sb + (uint32_t)(((rbase + mi * 16 + (lane & 15)) * AT2_STRIDE
                                     + qcol + ks + ((lane >> 4) << 3)) * 2));
        uint32_t b[8][2];
#pragma unroll
        for (int ni = 0; ni < 4; ni++) {
            uint32_t r0, r1, r2, r3;
            ldsm_x4(r0, r1, r2, r3,
                    sb + (uint32_t)(((ni * 16 + (lane & 7) + ((lane >> 4) << 3)) * AT2_STRIDE
                                     + kcol + ks + (((lane >> 3) & 1) << 3)) * 2));
            b[ni * 2][0] = r0; b[ni * 2][1] = r1;
            b[ni * 2 + 1][0] = r2; b[ni * 2 + 1][1] = r3;
        }
#pragma unroll
        for (int mi = 0; mi < 2; mi++)
#pragma unroll
            for (int nj = 0; nj < 8; nj++)
                mma16816(s[mi][nj], a[mi], b[nj]);
    }

    // ---- scale + bias (+ shift-mask only for boundary windows), row max ----
    const int wi = win & 63;
    const int wr = (wi >> 3) << 3, wc = (wi & 7) << 3;
    const bool domask = (wr > 48) || (wc > 48);   // reg3 nonzero only for p>=56
    const float scale = 0.17677669529663687f;
    float mx[2][2] = {{-1e30f,-1e30f},{-1e30f,-1e30f}};
    if (domask) {
#pragma unroll
        for (int mi = 0; mi < 2; mi++)
#pragma unroll
            for (int h8 = 0; h8 < 2; h8++) {
                int qi = rbase + mi * 16 + (lane >> 2) + h8 * 8;
                int qri = qi >> 3, qci = qi & 7;
                int myid = reg3(wr + qri) * 3 + reg3(wc + qci);
#pragma unroll
                for (int nj = 0; nj < 8; nj++)
#pragma unroll
                    for (int e = 0; e < 2; e++) {
                        int kj = nj * 8 + ((lane & 3) << 1) + e;
                        int krj = kj >> 3, kcj = kj & 7;
                        float v = fmaf(s[mi][nj][h8 * 2 + e], scale,
                                       bias_sm[(((qri - krj + 7) * 15 + qci - kcj + 7) << 3) + h]);
                        int jid = reg3(wr + krj) * 3 + reg3(wc + kcj);
                        if (jid != myid) v -= 100.f;
                        s[mi][nj][h8 * 2 + e] = v;
                        mx[mi][h8] = fmaxf(mx[mi][h8], v);
                    }
            }
    } else {
#pragma unroll
        for (int mi = 0; mi < 2; mi++)
#pragma unroll
            for (int h8 = 0; h8 < 2; h8++) {
                int qi = rbase + mi * 16 + (lane >> 2) + h8 * 8;
                int qri = qi >> 3, qci = qi & 7;
#pragma unroll
                for (int nj = 0; nj < 8; nj++)
#pragma unroll
                    for (int e = 0; e < 2; e++) {
                        int kj = nj * 8 + ((lane & 3) << 1) + e;
                        float v = fmaf(s[mi][nj][h8 * 2 + e], scale,
                                       bias_sm[(((qri - (kj >> 3) + 7) * 15
                                                 + qci - (kj & 7) + 7) << 3) + h]);
                        s[mi][nj][h8 * 2 + e] = v;
                        mx[mi][h8] = fmaxf(mx[mi][h8], v);
                    }
            }
    }
#pragma unroll
    for (int mi = 0; mi < 2; mi++)
#pragma unroll
        for (int h8 = 0; h8 < 2; h8++) {
            mx[mi][h8] = fmaxf(mx[mi][h8], __shfl_xor_sync(0xffffffffu, mx[mi][h8], 1));
            mx[mi][h8] = fmaxf(mx[mi][h8], __shfl_xor_sync(0xffffffffu, mx[mi][h8], 2));
        }

    // ---- exp + row sum ----
    float sum[2][2] = {{0,0},{0,0}};
#pragma unroll
    for (int mi = 0; mi < 2; mi++)
#pragma unroll
        for (int nj = 0; nj < 8; nj++)
#pragma unroll
            for (int e4 = 0; e4 < 4; e4++) {
                int h8 = e4 >> 1;
                float v = __expf(s[mi][nj][e4] - mx[mi][h8]);
                s[mi][nj][e4] = v;
                sum[mi][h8] += v;
            }
    float inv[2][2];
#pragma unroll
    for (int mi = 0; mi < 2; mi++)
#pragma unroll
        for (int h8 = 0; h8 < 2; h8++) {
            float t = sum[mi][h8];
            t += __shfl_xor_sync(0xffffffffu, t, 1);
            t += __shfl_xor_sync(0xffffffffu, t, 2);
            inv[mi][h8] = __frcp_rn(t);
        }

    // ---- pack P ----
    uint32_t p[2][4][4];
#pragma unroll
    for (int mi = 0; mi < 2; mi++)
#pragma unroll
        for (int ks = 0; ks < 4; ks++) {
            p[mi][ks][0] = bf2_to_u32(s[mi][2*ks][0],   s[mi][2*ks][1]);
            p[mi][ks][1] = bf2_to_u32(s[mi][2*ks][2],   s[mi][2*ks][3]);
            p[mi][ks][2] = bf2_to_u32(s[mi][2*ks+1][0], s[mi][2*ks+1][1]);
            p[mi][ks][3] = bf2_to_u32(s[mi][2*ks+1][2], s[mi][2*ks+1][3]);
        }

    // ---- O = P @ V ----
    float o[2][4][4];
#pragma unroll
    for (int mi = 0; mi < 2; mi++)
#pragma unroll
        for (int dj = 0; dj < 4; dj++)
#pragma unroll
            for (int e = 0; e < 4; e++) o[mi][dj][e] = 0.f;

#pragma unroll
    for (int ks = 0; ks < 4; ks++) {
        uint32_t vb[4][2];
#pragma unroll
        for (int dt = 0; dt < 2; dt++) {
            uint32_t r0, r1, r2, r3;
            ldsm_x4_trans(r0, r1, r2, r3,
                sb + (uint32_t)(((ks * 16 + (lane & 7) + (((lane >> 3) & 1) << 3)) * AT2_STRIDE
                                 + vcol + dt * 16 + ((lane >> 4) << 3)) * 2));
            vb[dt * 2][0] = r0; vb[dt * 2][1] = r1;
            vb[dt * 2 + 1][0] = r2; vb[dt * 2 + 1][1] = r3;
        }
#pragma unroll
        for (int mi = 0; mi < 2; mi++)
#pragma unroll
            for (int dj = 0; dj < 4; dj++)
                mma16816(o[mi][dj], p[mi][ks], vb[dj]);
    }

    // ---- normalize + store ----
#pragma unroll
    for (int mi = 0; mi < 2; mi++)
#pragma unroll
        for (int dj = 0; dj < 4; dj++)
#pragma unroll
            for (int h8 = 0; h8 < 2; h8++) {
                int row = rbase + mi * 16 + (lane >> 2) + h8 * 8;
                int col = dj * 8 + ((lane & 3) << 1);
                __nv_bfloat162 ov = __floats2bfloat162_rn(
                    o[mi][dj][h8 * 2]     * inv[mi][h8],
                    o[mi][dj][h8 * 2 + 1] * inv[mi][h8]);
                *(__nv_bfloat162*)(out + (size_t)(win * 64 + row) * 256 + h * 32 + col) = ov;
            }
}

// ---------------- residual (window-reverse + unshift) + LN2 ----------------
__global__ void k_resid_ln2(const float* __restrict__ x, const __nv_bfloat16* __restrict__ proj,
                            const float* __restrict__ w, const float* __restrict__ bb,
                            __nv_bfloat16* __restrict__ ln2) {
    int gw = (blockIdx.x * blockDim.x + threadIdx.x) >> 5;
    int lane = threadIdx.x & 31;
    if (gw >= MTOK) return;
    int b = gw >> 12, pos = gw & 4095;
    int hh = pos >> 6, ww = pos & 63;
    int hs = (hh - CSS) & 63, ws = (ww - CSS) & 63;
    int m = (b << 12) + ((((hs >> 3) << 3) + (ws >> 3)) << 6) + ((hs & 7) << 3) + (ws & 7);
    const float4* xr = (const float4*)(x + (size_t)gw * CC);
    float4 a = xr[lane * 2], c = xr[lane * 2 + 1];
    uint4 pu = *(const uint4*)(proj + (size_t)m * CC + lane * 8);
    const __nv_bfloat162* p2 = (const __nv_bfloat162*)&pu;
    float2 f0 = __bfloat1622float2(p2[0]);
    float2 f1 = __bfloat1622float2(p2[1]);
    float2 f2 = __bfloat1622float2(p2[2]);
    float2 f3 = __bfloat1622float2(p2[3]);
    a.x += f0.x; a.y += f0.y; a.z += f1.x; a.w += f1.y;
    c.x += f2.x; c.y += f2.y; c.z += f3.x; c.w += f3.y;
    float s  = a.x + a.y + a.z + a.w + c.x + c.y + c.z + c.w;
    float sq = a.x*a.x + a.y*a.y + a.z*a.z + a.w*a.w + c.x*c.x + c.y*c.y + c.z*c.z + c.w*c.w;
    s = warp_sum(s); sq = warp_sum(sq);
    float mean = s * (1.f / 256.f);
    float var  = sq * (1.f / 256.f) - mean * mean;
    float rs   = rsqrtf(var + 1e-5f);
    const float4* wp = (const float4*)w;
    const float4* bp = (const float4*)bb;
    float4 w0v = wp[lane * 2], w1v = wp[lane * 2 + 1];
    float4 b0v = bp[lane * 2], b1v = bp[lane * 2 + 1];
    __align__(16) __nv_bfloat16 o8[8];
    o8[0] = __float2bfloat16((a.x - mean) * rs * w0v.x + b0v.x);
    o8[1] = __float2bfloat16((a.y - mean) * rs * w0v.y + b0v.y);
    o8[2] = __float2bfloat16((a.z - mean) * rs * w0v.z + b0v.z);
    o8[3] = __float2bfloat16((a.w - mean) * rs * w0v.w + b0v.w);
    o8[4] = __float2bfloat16((c.x - mean) * rs * w1v.x + b1v.x);
    o8[5] = __float2bfloat16((c.y - mean) * rs * w1v.y + b1v.y);
    o8[6] = __float2bfloat16((c.z - mean) * rs * w1v.z + b1v.z);
    o8[7] = __float2bfloat16((c.w - mean) * rs * w1v.w + b1v.w);
    *(uint4*)(ln2 + (size_t)gw * CC + lane * 8) = *(const uint4*)o8;
}

// ---------------- launcher ----------------
extern "C" void kernel_launch(void* const* d_in, const int* in_sizes, int n_in,
                              void* d_out, int out_size) {
    const float* x     = (const float*)d_in[0];
    const float* n1w   = (const float*)d_in[1];
    const float* n1b   = (const float*)d_in[2];
    const float* qkvw  = (const float*)d_in[3];
    const float* qkvb  = (const float*)d_in[4];
    const float* projw = (const float*)d_in[5];
    const float* projb = (const float*)d_in[6];
    const float* rpb   = (const float*)d_in[7];
    const float* n2w   = (const float*)d_in[8];
    const float* n2b   = (const float*)d_in[9];
    const float* f12w  = (const float*)d_in[10];
    const float* f12b  = (const float*)d_in[11];
    const float* f2w   = (const float*)d_in[12];
    const float* f2b   = (const float*)d_in[13];
    float* out = (float*)d_out;

    void *p_hw, *p_qkv, *p_att, *p_proj, *p_ln2, *p_gat;
    void *p_wq, *p_wp, *p_w12, *p_b12, *p_w2;
    cudaGetSymbolAddress(&p_hw, g_hw);
    cudaGetSymbolAddress(&p_qkv, g_qkv);
    cudaGetSymbolAddress(&p_att, g_att);
    cudaGetSymbolAddress(&p_proj, g_proj);
    cudaGetSymbolAddress(&p_ln2, g_ln2);
    cudaGetSymbolAddress(&p_gat, g_gat);
    cudaGetSymbolAddress(&p_wq, g_wqkv);
    cudaGetSymbolAddress(&p_wp, g_wproj);
    cudaGetSymbolAddress(&p_w12, g_wf12r);
    cudaGetSymbolAddress(&p_b12, g_b12r);
    cudaGetSymbolAddress(&p_w2, g_wf2);

    cudaFuncSetAttribute(k_gemm3<0>, cudaFuncAttributeMaxDynamicSharedMemorySize, M3_SMEM);
    cudaFuncSetAttribute(k_gemm3<3>, cudaFuncAttributeMaxDynamicSharedMemorySize, M3_SMEM);
    cudaFuncSetAttribute(k_gemm3<4>, cudaFuncAttributeMaxDynamicSharedMemorySize, M3_SMEM);
    cudaFuncSetAttribute(k_attn2,    cudaFuncAttributeMaxDynamicSharedMemorySize, AT2_SMEM);

    // one prep launch for all weights
    k_prep<<<2048, 256>>>(qkvw, projw, f2w, f12w, f12b,
                          (__nv_bfloat16*)p_wq, (__nv_bfloat16*)p_wp,
                          (__nv_bfloat16*)p_w2, (__nv_bfloat16*)p_w12, (float*)p_b12);

    // LN1 + shift + window partition
    k_ln1_shift<<<16384, 256>>>(x, n1w, n1b, (__nv_bfloat16*)p_hw);

    // qkv: [131072,256] @ [768,256]^T -> bf16
    k_gemm3<0><<<dim3(6, MTOK / 128), 256, M3_SMEM>>>(
        (const __nv_bfloat16*)p_hw, (const __nv_bfloat16*)p_wq, qkvb,
        p_qkv, nullptr, nullptr, MTOK, 768, 256);

    // tensor-core windowed attention (4 heads per CTA, 2 CTAs per window, 2 CTAs/SM)
    k_attn2<<<4096, 256, AT2_SMEM>>>((const __nv_bfloat16*)p_qkv, rpb,
                                     (__nv_bfloat16*)p_att);

    // proj -> bf16 (window order)
    k_gemm3<0><<<dim3(2, MTOK / 128), 256, M3_SMEM>>>(
        (const __nv_bfloat16*)p_att, (const __nv_bfloat16*)p_wp, projb,
        p_proj, nullptr, nullptr, MTOK, 256, 256);

    // residual (window reverse + unshift) + LN2
    k_resid_ln2<<<16384, 256>>>(x, (const __nv_bfloat16*)p_proj, n2w, n2b,
                                (__nv_bfloat16*)p_ln2);

    // fc12 (fused SiLU gate): [131072,256] @ [2048,256]^T -> [131072,1024] bf16
    k_gemm3<3><<<dim3(16, MTOK / 128), 256, M3_SMEM>>>(
        (const __nv_bfloat16*)p_ln2, (const __nv_bfloat16*)p_w12, (const float*)p_b12,
        p_gat, nullptr, nullptr, MTOK, 2048, 256);

    // fc2 + recomputed residual (x + proj) -> d_out fp32
    k_gemm3<4><<<dim3(2, MTOK / 128), 256, M3_SMEM>>>(
        (const __nv_bfloat16*)p_gat, (const __nv_bfloat16*)p_w2, f2b,
        out, x, (const __nv_bfloat16*)p_proj, MTOK, 256, 1024);
}